// round 13
// baseline (speedup 1.0000x reference)
#include <cuda_runtime.h>
#include <cuda_fp16.h>
#include <math.h>
#include <stdint.h>

#define NN 10000
#define EE 160000
#define FIN 70
#define KP 80            // FIN padded to multiple of 16
#define HHID 256
#define D1 1024          // HEADS*HID

typedef unsigned long long u64;

__device__ __forceinline__ uint32_t smem_u32(const void* p) {
    uint32_t a;
    asm("{ .reg .u64 t; cvta.to.shared.u64 t, %1; cvt.u32.u64 %0, t; }" : "=r"(a) : "l"(p));
    return a;
}
__device__ __forceinline__ float4 h4_to_f4(u64 v) {
    __half2 lo = reinterpret_cast<__half2*>(&v)[0];
    __half2 hi = reinterpret_cast<__half2*>(&v)[1];
    float2 a = __half22float2(lo), b = __half22float2(hi);
    return make_float4(a.x, a.y, b.x, b.y);
}

// ---------------- device scratch (no allocations allowed) ----------------
__device__ __align__(16) __half g_h1h[NN * D1];   // layer-1 linear out (fp16)
__device__ __align__(16) __half g_x1h[NN * D1];   // relu(agg1+b1) fp16 (GEMM2 A)
__device__ __align__(16) __half g_w1h[D1 * KP];   // W1^T fp16 [n][k], k padded to 80
__device__ __align__(16) __half g_w2h[HHID * D1]; // W2^T fp16 [n][k]
__device__ __align__(16) float g_as1[NN * 4];
__device__ __align__(16) float g_ad1[NN * 4];
__device__ __align__(16) float g_h2[NN * HHID];   // layer-2 linear out (fp32)
__device__ float g_as2[NN];
__device__ float g_ad2[NN];
__device__ __align__(16) float g_ex1s[EE * 4];    // exp(leaky) per edge, DST-SORTED
__device__ float g_ex2s[EE];
__device__ __align__(16) float g_exself1[NN * 4];
__device__ __align__(16) float g_den1[NN * 4];
__device__ float g_exself2[NN];
__device__ float g_den2[NN];
__device__ float g_pooled[HHID];
__device__ int   g_deg[NN];
__device__ int   g_offs[NN + 1];
__device__ int   g_cursor[NN];
__device__ int   g_srcs[EE];
__device__ int   g_pos[EE];      // original edge -> sorted slot

// ---------------- setup chain ----------------
__global__ void k_zerodeg() {
    int i = blockIdx.x * blockDim.x + threadIdx.x;
    if (i < NN) g_deg[i] = 0;
}

__global__ void k_hist(const int* __restrict__ ei) {
    int i = blockIdx.x * blockDim.x + threadIdx.x;
    if (i < EE) atomicAdd(&g_deg[ei[EE + i]], 1);
}

__global__ void k_scan() {
    __shared__ int sbuf[1024];
    int t = threadIdx.x;
    int base = t * 10;
    int loc[10];
    int sum = 0;
#pragma unroll
    for (int q = 0; q < 10; q++) {
        int idx = base + q;
        int v = (idx < NN) ? g_deg[idx] : 0;
        loc[q] = sum; sum += v;
    }
    sbuf[t] = sum;
    __syncthreads();
    for (int off = 1; off < 1024; off <<= 1) {
        int tmp = (t >= off) ? sbuf[t - off] : 0;
        __syncthreads();
        sbuf[t] += tmp;
        __syncthreads();
    }
    int excl = sbuf[t] - sum;
#pragma unroll
    for (int q = 0; q < 10; q++) {
        int idx = base + q;
        if (idx < NN) { int o = excl + loc[q]; g_offs[idx] = o; g_cursor[idx] = o; }
    }
    if (t == 1023) g_offs[NN] = sbuf[1023];
}

__global__ void k_scatter(const int* __restrict__ ei) {
    int i = blockIdx.x * blockDim.x + threadIdx.x;
    if (i < EE) {
        int dnode = ei[EE + i];
        int pos = atomicAdd(&g_cursor[dnode], 1);
        g_srcs[pos] = ei[i];
        g_pos[i] = pos;
    }
}

// ---------------- prep: pooled zero + W1 -> fp16 transpose --------------
__global__ void k_prep(const float* __restrict__ W1) {
    int id = blockIdx.x * blockDim.x + threadIdx.x;
    if (id < KP * D1) {
        int k = id >> 10, n = id & 1023;
        float v = (k < FIN) ? W1[k * D1 + n] : 0.f;
        g_w1h[(size_t)n * KP + k] = __float2half(v);
    } else if (id < KP * D1 + HHID) {
        g_pooled[id - KP * D1] = 0.f;
    }
}

// ---------------- W2 [1024,256] fp32 -> g_w2h [256][1024] fp16 ----------
__global__ void k_prepW2(const float* __restrict__ W2) {
    __shared__ float t[32][33];
    int k0 = blockIdx.x * 32, n0 = blockIdx.y * 32;
    int tx = threadIdx.x & 31, ty = threadIdx.x >> 5;   // 256 threads
#pragma unroll
    for (int i = 0; i < 4; i++)
        t[ty + 8 * i][tx] = W2[(k0 + ty + 8 * i) * HHID + n0 + tx];
    __syncthreads();
#pragma unroll
    for (int i = 0; i < 4; i++)
        g_w2h[(size_t)(n0 + ty + 8 * i) * D1 + k0 + tx] = __float2half(t[tx][ty + 8 * i]);
}

// ---------------- GEMM1 via HMMA: x[N,70] @ W1 -> g_h1h (fp16) ----------
#define G1_LDS 88
__global__ void __launch_bounds__(256) k_gemm1(const float* __restrict__ x) {
    __shared__ __align__(16) __half As[128][G1_LDS];
    __shared__ __align__(16) __half Bs[128][G1_LDS];
    int tid = threadIdx.x, lane = tid & 31, w = tid >> 5;
    int wm = w >> 2, wn = w & 3;
    int row0 = blockIdx.x * 128;
    int col0 = blockIdx.y * 128;

    for (int idx = tid; idx < 128 * KP; idx += 256) {
        int r = idx / KP, c = idx - r * KP;
        float v = 0.f;
        if (c < FIN && row0 + r < NN) v = x[(size_t)(row0 + r) * FIN + c];
        As[r][c] = __float2half(v);
    }
    for (int idx = tid; idx < 128 * 10; idx += 256) {
        int r = idx / 10, q = idx - r * 10;
        *reinterpret_cast<uint4*>(&Bs[r][q * 8]) =
            *reinterpret_cast<const uint4*>(&g_w1h[(size_t)(col0 + r) * KP + q * 8]);
    }
    __syncthreads();

    float acc[4][4][4];
#pragma unroll
    for (int i = 0; i < 4; i++)
#pragma unroll
        for (int j = 0; j < 4; j++)
#pragma unroll
            for (int q = 0; q < 4; q++) acc[i][j][q] = 0.f;

#pragma unroll
    for (int kh = 0; kh < 5; kh++) {
        uint32_t af[4][4], bf[4][2];
#pragma unroll
        for (int mt = 0; mt < 4; mt++) {
            int r = wm * 64 + mt * 16 + (lane & 15);
            int c = kh * 16 + (lane >> 4) * 8;
            uint32_t a = smem_u32(&As[r][c]);
            asm volatile("ldmatrix.sync.aligned.m8n8.x4.shared.b16 {%0,%1,%2,%3}, [%4];"
                : "=r"(af[mt][0]), "=r"(af[mt][1]), "=r"(af[mt][2]), "=r"(af[mt][3]) : "r"(a));
        }
#pragma unroll
        for (int nt = 0; nt < 4; nt++) {
            int r = wn * 32 + nt * 8 + (lane & 7);
            int c = kh * 16 + ((lane >> 3) & 1) * 8;
            uint32_t a = smem_u32(&Bs[r][c]);
            asm volatile("ldmatrix.sync.aligned.m8n8.x2.shared.b16 {%0,%1}, [%2];"
                : "=r"(bf[nt][0]), "=r"(bf[nt][1]) : "r"(a));
        }
#pragma unroll
        for (int mt = 0; mt < 4; mt++)
#pragma unroll
            for (int nt = 0; nt < 4; nt++)
                asm volatile(
                    "mma.sync.aligned.m16n8k16.row.col.f32.f16.f16.f32 "
                    "{%0,%1,%2,%3},{%4,%5,%6,%7},{%8,%9},{%0,%1,%2,%3};"
                    : "+f"(acc[mt][nt][0]), "+f"(acc[mt][nt][1]),
                      "+f"(acc[mt][nt][2]), "+f"(acc[mt][nt][3])
                    : "r"(af[mt][0]), "r"(af[mt][1]), "r"(af[mt][2]), "r"(af[mt][3]),
                      "r"(bf[nt][0]), "r"(bf[nt][1]));
    }

#pragma unroll
    for (int mt = 0; mt < 4; mt++) {
        int rr = row0 + wm * 64 + mt * 16 + (lane >> 2);
#pragma unroll
        for (int nt = 0; nt < 4; nt++) {
            int cc = col0 + wn * 32 + nt * 8 + 2 * (lane & 3);
            if (rr < NN)
                *reinterpret_cast<__half2*>(&g_h1h[(size_t)rr * D1 + cc]) =
                    __floats2half2_rn(acc[mt][nt][0], acc[mt][nt][1]);
            if (rr + 8 < NN)
                *reinterpret_cast<__half2*>(&g_h1h[(size_t)(rr + 8) * D1 + cc]) =
                    __floats2half2_rn(acc[mt][nt][2], acc[mt][nt][3]);
        }
    }
}

// ---------------- attention logits layer 1 + self-loop ex + den init ---
__global__ void k_att1(const float* __restrict__ as, const float* __restrict__ adv) {
    int wid = threadIdx.x >> 5, lane = threadIdx.x & 31;
    int d = blockIdx.x;
    const u64* hb = reinterpret_cast<const u64*>(g_h1h + (size_t)d * D1 + wid * 256);
    const float4* as4 = reinterpret_cast<const float4*>(as  + wid * 256);
    const float4* ad4 = reinterpret_cast<const float4*>(adv + wid * 256);
    float ps = 0.f, pd = 0.f;
#pragma unroll
    for (int t = 0; t < 2; t++) {
        int p = lane + 32 * t;
        float4 f = h4_to_f4(hb[p]);
        float4 a = as4[p], b = ad4[p];
        ps += f.x * a.x + f.y * a.y + f.z * a.z + f.w * a.w;
        pd += f.x * b.x + f.y * b.y + f.z * b.z + f.w * b.w;
    }
#pragma unroll
    for (int o = 16; o; o >>= 1) {
        ps += __shfl_xor_sync(0xffffffffu, ps, o);
        pd += __shfl_xor_sync(0xffffffffu, pd, o);
    }
    if (lane == 0) {
        g_as1[d * 4 + wid] = ps; g_ad1[d * 4 + wid] = pd;
        float e = ps + pd;
        e = e > 0.f ? e : 0.2f * e;
        float ex = expf(e);
        g_exself1[d * 4 + wid] = ex;
        g_den1[d * 4 + wid] = ex;
    }
}

// ---------------- edge kernel layer 1: ex (sorted) + denom atomics -----
__global__ void k_edge1(const int* __restrict__ ei) {
    int i = blockIdx.x * blockDim.x + threadIdx.x;
    if (i >= EE) return;
    int s = ei[i], d = ei[EE + i];
    float4 a = *reinterpret_cast<const float4*>(&g_as1[s * 4]);
    float4 b = *reinterpret_cast<const float4*>(&g_ad1[d * 4]);
    float e0 = a.x + b.x; e0 = e0 > 0.f ? e0 : 0.2f * e0; e0 = expf(e0);
    float e1 = a.y + b.y; e1 = e1 > 0.f ? e1 : 0.2f * e1; e1 = expf(e1);
    float e2 = a.z + b.z; e2 = e2 > 0.f ? e2 : 0.2f * e2; e2 = expf(e2);
    float e3 = a.w + b.w; e3 = e3 > 0.f ? e3 : 0.2f * e3; e3 = expf(e3);
    int pos = g_pos[i];
    *reinterpret_cast<float4*>(&g_ex1s[(size_t)pos * 4]) = make_float4(e0, e1, e2, e3);
    atomicAdd(&g_den1[d * 4 + 0], e0);
    atomicAdd(&g_den1[d * 4 + 1], e1);
    atomicAdd(&g_den1[d * 4 + 2], e2);
    atomicAdd(&g_den1[d * 4 + 3], e3);
}

// ---------------- layer-1 aggregation: 128 thr x 8 ch (uint4) ----------
// thread t handles channels [8t, 8t+8) -> head h = t>>5 (warp-uniform ex)
__global__ void k_agg1(const float* __restrict__ b1) {
    int d = blockIdx.x, t = threadIdx.x;
    int beg = g_offs[d], cnt = g_offs[d + 1] - beg;
    int h = t >> 5;
    const uint4* hb = reinterpret_cast<const uint4*>(g_h1h);

    float acc[8];
    {
        float ex = g_exself1[d * 4 + h];
        uint4 v = hb[(size_t)d * 128 + t];
        float4 f0 = h4_to_f4(*reinterpret_cast<u64*>(&v.x));
        float4 f1 = h4_to_f4(*reinterpret_cast<u64*>(&v.z));
        acc[0] = ex * f0.x; acc[1] = ex * f0.y; acc[2] = ex * f0.z; acc[3] = ex * f0.w;
        acc[4] = ex * f1.x; acc[5] = ex * f1.y; acc[6] = ex * f1.z; acc[7] = ex * f1.w;
    }

#pragma unroll 4
    for (int i = 0; i < cnt; i++) {
        int s = g_srcs[beg + i];
        float e = g_ex1s[(size_t)(beg + i) * 4 + h];
        uint4 v = hb[(size_t)s * 128 + t];
        float4 f0 = h4_to_f4(*reinterpret_cast<u64*>(&v.x));
        float4 f1 = h4_to_f4(*reinterpret_cast<u64*>(&v.z));
        acc[0] += e * f0.x; acc[1] += e * f0.y; acc[2] += e * f0.z; acc[3] += e * f0.w;
        acc[4] += e * f1.x; acc[5] += e * f1.y; acc[6] += e * f1.z; acc[7] += e * f1.w;
    }

    float inv = 1.f / (g_den1[d * 4 + h] + 1e-16f);
    float4 bb0 = *reinterpret_cast<const float4*>(&b1[8 * t]);
    float4 bb1 = *reinterpret_cast<const float4*>(&b1[8 * t + 4]);
    uint4 outv;
    reinterpret_cast<__half2*>(&outv)[0] = __floats2half2_rn(fmaxf(acc[0] * inv + bb0.x, 0.f),
                                                            fmaxf(acc[1] * inv + bb0.y, 0.f));
    reinterpret_cast<__half2*>(&outv)[1] = __floats2half2_rn(fmaxf(acc[2] * inv + bb0.z, 0.f),
                                                            fmaxf(acc[3] * inv + bb0.w, 0.f));
    reinterpret_cast<__half2*>(&outv)[2] = __floats2half2_rn(fmaxf(acc[4] * inv + bb1.x, 0.f),
                                                            fmaxf(acc[5] * inv + bb1.y, 0.f));
    reinterpret_cast<__half2*>(&outv)[3] = __floats2half2_rn(fmaxf(acc[6] * inv + bb1.z, 0.f),
                                                            fmaxf(acc[7] * inv + bb1.w, 0.f));
    *reinterpret_cast<uint4*>(&g_x1h[(size_t)d * D1 + 8 * t]) = outv;
}

// ---------------- GEMM2 via mma.sync (HMMA fp16) ------------------------
#define MM_BM 128
#define MM_BN 128
#define MM_BK 32
#define MM_LDS 40      // row stride in halves (32 + 8 pad)
__global__ void __launch_bounds__(256) k_gemm2(int dummy) {
    __shared__ __align__(16) __half As[MM_BM][MM_LDS];
    __shared__ __align__(16) __half Bs[MM_BN][MM_LDS];
    int tid = threadIdx.x, lane = tid & 31, w = tid >> 5;
    int wm = w >> 2, wn = w & 3;
    int row0 = blockIdx.x * MM_BM;
    int col0 = blockIdx.y * MM_BN;

    float acc[4][4][4];
#pragma unroll
    for (int i = 0; i < 4; i++)
#pragma unroll
        for (int j = 0; j < 4; j++)
#pragma unroll
            for (int q = 0; q < 4; q++) acc[i][j][q] = 0.f;

    int rA0 = (tid + 0)   >> 2, qA0 = (tid + 0)   & 3;
    int rA1 = (tid + 256) >> 2, qA1 = (tid + 256) & 3;

    uint4 pa0, pa1, pb0, pb1;
    {
        pa0 = make_uint4(0, 0, 0, 0); pa1 = make_uint4(0, 0, 0, 0);
        if (row0 + rA0 < NN)
            pa0 = *reinterpret_cast<const uint4*>(&g_x1h[(size_t)(row0 + rA0) * D1 + qA0 * 8]);
        if (row0 + rA1 < NN)
            pa1 = *reinterpret_cast<const uint4*>(&g_x1h[(size_t)(row0 + rA1) * D1 + qA1 * 8]);
        pb0 = *reinterpret_cast<const uint4*>(&g_w2h[(size_t)(col0 + rA0) * D1 + qA0 * 8]);
        pb1 = *reinterpret_cast<const uint4*>(&g_w2h[(size_t)(col0 + rA1) * D1 + qA1 * 8]);
    }

    for (int kc = 0; kc < D1; kc += MM_BK) {
        *reinterpret_cast<uint4*>(&As[rA0][qA0 * 8]) = pa0;
        *reinterpret_cast<uint4*>(&As[rA1][qA1 * 8]) = pa1;
        *reinterpret_cast<uint4*>(&Bs[rA0][qA0 * 8]) = pb0;
        *reinterpret_cast<uint4*>(&Bs[rA1][qA1 * 8]) = pb1;
        __syncthreads();

        if (kc + MM_BK < D1) {
            int kn = kc + MM_BK;
            pa0 = make_uint4(0, 0, 0, 0); pa1 = make_uint4(0, 0, 0, 0);
            if (row0 + rA0 < NN)
                pa0 = *reinterpret_cast<const uint4*>(&g_x1h[(size_t)(row0 + rA0) * D1 + kn + qA0 * 8]);
            if (row0 + rA1 < NN)
                pa1 = *reinterpret_cast<const uint4*>(&g_x1h[(size_t)(row0 + rA1) * D1 + kn + qA1 * 8]);
            pb0 = *reinterpret_cast<const uint4*>(&g_w2h[(size_t)(col0 + rA0) * D1 + kn + qA0 * 8]);
            pb1 = *reinterpret_cast<const uint4*>(&g_w2h[(size_t)(col0 + rA1) * D1 + kn + qA1 * 8]);
        }

#pragma unroll
        for (int kh = 0; kh < 2; kh++) {
            uint32_t af[4][4], bf[4][2];
#pragma unroll
            for (int mt = 0; mt < 4; mt++) {
                int r = wm * 64 + mt * 16 + (lane & 15);
                int c = kh * 16 + (lane >> 4) * 8;
                uint32_t a = smem_u32(&As[r][c]);
                asm volatile("ldmatrix.sync.aligned.m8n8.x4.shared.b16 {%0,%1,%2,%3}, [%4];"
                    : "=r"(af[mt][0]), "=r"(af[mt][1]), "=r"(af[mt][2]), "=r"(af[mt][3]) : "r"(a));
            }
#pragma unroll
            for (int nt = 0; nt < 4; nt++) {
                int r = wn * 32 + nt * 8 + (lane & 7);
                int c = kh * 16 + ((lane >> 3) & 1) * 8;
                uint32_t a = smem_u32(&Bs[r][c]);
                asm volatile("ldmatrix.sync.aligned.m8n8.x2.shared.b16 {%0,%1}, [%2];"
                    : "=r"(bf[nt][0]), "=r"(bf[nt][1]) : "r"(a));
            }
#pragma unroll
            for (int mt = 0; mt < 4; mt++)
#pragma unroll
                for (int nt = 0; nt < 4; nt++)
                    asm volatile(
                        "mma.sync.aligned.m16n8k16.row.col.f32.f16.f16.f32 "
                        "{%0,%1,%2,%3},{%4,%5,%6,%7},{%8,%9},{%0,%1,%2,%3};"
                        : "+f"(acc[mt][nt][0]), "+f"(acc[mt][nt][1]),
                          "+f"(acc[mt][nt][2]), "+f"(acc[mt][nt][3])
                        : "r"(af[mt][0]), "r"(af[mt][1]), "r"(af[mt][2]), "r"(af[mt][3]),
                          "r"(bf[nt][0]), "r"(bf[nt][1]));
        }
        __syncthreads();
    }

#pragma unroll
    for (int mt = 0; mt < 4; mt++) {
        int rr = row0 + wm * 64 + mt * 16 + (lane >> 2);
#pragma unroll
        for (int nt = 0; nt < 4; nt++) {
            int cc = col0 + wn * 32 + nt * 8 + 2 * (lane & 3);
            if (rr < NN)
                *reinterpret_cast<float2*>(&g_h2[(size_t)rr * HHID + cc]) =
                    make_float2(acc[mt][nt][0], acc[mt][nt][1]);
            if (rr + 8 < NN)
                *reinterpret_cast<float2*>(&g_h2[(size_t)(rr + 8) * HHID + cc]) =
                    make_float2(acc[mt][nt][2], acc[mt][nt][3]);
        }
    }
}

// ---------------- attention logits layer 2 + self ex + den init --------
__global__ void k_att2(const float* __restrict__ as, const float* __restrict__ adv) {
    int wid = threadIdx.x >> 5, lane = threadIdx.x & 31;
    int d = blockIdx.x * 4 + wid;
    if (d >= NN) return;
    const float4* h4  = reinterpret_cast<const float4*>(g_h2 + (size_t)d * HHID);
    const float4* as4 = reinterpret_cast<const float4*>(as);
    const float4* ad4 = reinterpret_cast<const float4*>(adv);
    float ps = 0.f, pd = 0.f;
#pragma unroll
    for (int t = 0; t < 2; t++) {
        int p = lane + 32 * t;
        float4 f = h4[p];
        float4 a = as4[p], b = ad4[p];
        ps += f.x * a.x + f.y * a.y + f.z * a.z + f.w * a.w;
        pd += f.x * b.x + f.y * b.y + f.z * b.z + f.w * b.w;
    }
#pragma unroll
    for (int o = 16; o; o >>= 1) {
        ps += __shfl_xor_sync(0xffffffffu, ps, o);
        pd += __shfl_xor_sync(0xffffffffu, pd, o);
    }
    if (lane == 0) {
        g_as2[d] = ps; g_ad2[d] = pd;
        float e = ps + pd;
        e = e > 0.f ? e : 0.2f * e;
        float ex = expf(e);
        g_exself2[d] = ex;
        g_den2[d] = ex;
    }
}

// ---------------- edge kernel layer 2 ----------------------------------
__global__ void k_edge2(const int* __restrict__ ei) {
    int i = blockIdx.x * blockDim.x + threadIdx.x;
    if (i >= EE) return;
    int s = ei[i], d = ei[EE + i];
    float e = g_as2[s] + g_ad2[d];
    e = e > 0.f ? e : 0.2f * e;
    float ex = expf(e);
    g_ex2s[g_pos[i]] = ex;
    atomicAdd(&g_den2[d], ex);
}

// ---------------- layer-2 aggregation: 64 thr x 4 ch (float4) ----------
__global__ void k_agg2(const float* __restrict__ b2) {
    int d = blockIdx.x, t = threadIdx.x;   // 64 threads
    int beg = g_offs[d], cnt = g_offs[d + 1] - beg;
    const float4* h4 = reinterpret_cast<const float4*>(g_h2);

    float4 acc;
    {
        float ex = g_exself2[d];
        float4 f = h4[(size_t)d * 64 + t];
        acc = make_float4(ex * f.x, ex * f.y, ex * f.z, ex * f.w);
    }
#pragma unroll 4
    for (int i = 0; i < cnt; i++) {
        int s = g_srcs[beg + i];
        float e = g_ex2s[beg + i];
        float4 f = h4[(size_t)s * 64 + t];
        acc.x += e * f.x; acc.y += e * f.y; acc.z += e * f.z; acc.w += e * f.w;
    }
    float inv = 1.f / (g_den2[d] + 1e-16f);
    float4 bb = *reinterpret_cast<const float4*>(&b2[4 * t]);
    float v0 = fmaxf(acc.x * inv + bb.x, 0.f);
    float v1 = fmaxf(acc.y * inv + bb.y, 0.f);
    float v2 = fmaxf(acc.z * inv + bb.z, 0.f);
    float v3 = fmaxf(acc.w * inv + bb.w, 0.f);
    atomicAdd(&g_pooled[4 * t + 0], v0 * (1.0f / NN));
    atomicAdd(&g_pooled[4 * t + 1], v1 * (1.0f / NN));
    atomicAdd(&g_pooled[4 * t + 2], v2 * (1.0f / NN));
    atomicAdd(&g_pooled[4 * t + 3], v3 * (1.0f / NN));
}

// ---------------- final MLP ----------------
__global__ void k_final(const float* __restrict__ Wv1, const float* __restrict__ bv1,
                        const float* __restrict__ Wv2, const float* __restrict__ bv2,
                        float* __restrict__ out) {
    __shared__ float sp[HHID];
    __shared__ float wred[4];
    int t = threadIdx.x;   // 128 threads
    for (int c = t; c < HHID; c += 128) sp[c] = g_pooled[c];
    __syncthreads();
    float a = 0.f;
    for (int k = 0; k < HHID; k++) a += sp[k] * Wv1[k * 128 + t];
    a += bv1[t];
    float g = a * normcdff(a);
    float v = g * Wv2[t];
    int lane = t & 31, wid = t >> 5;
#pragma unroll
    for (int o = 16; o; o >>= 1) v += __shfl_xor_sync(0xffffffffu, v, o);
    if (lane == 0) wred[wid] = v;
    __syncthreads();
    if (t == 0) out[0] = wred[0] + wred[1] + wred[2] + wred[3] + bv2[0];
}

// ---------------- launch (single stream, linear) ----------------
extern "C" void kernel_launch(void* const* d_in, const int* in_sizes, int n_in,
                              void* d_out, int out_size) {
    const float* x       = (const float*)d_in[0];
    const int*   ei      = (const int*)  d_in[1];
    // d_in[2] edge_attr unused (GATConv built without edge_dim)
    const float* W1      = (const float*)d_in[3];
    const float* att_s1  = (const float*)d_in[4];
    const float* att_d1  = (const float*)d_in[5];
    const float* b1      = (const float*)d_in[6];
    const float* W2      = (const float*)d_in[7];
    const float* att_s2  = (const float*)d_in[8];
    const float* att_d2  = (const float*)d_in[9];
    const float* b2      = (const float*)d_in[10];
    const float* Wv1     = (const float*)d_in[11];
    const float* bv1     = (const float*)d_in[12];
    const float* Wv2     = (const float*)d_in[13];
    const float* bv2     = (const float*)d_in[14];
    float* out = (float*)d_out;

    k_zerodeg<<<(NN + 255) / 256, 256>>>();
    k_hist<<<(EE + 255) / 256, 256>>>(ei);
    k_scan<<<1, 1024>>>();
    k_scatter<<<(EE + 255) / 256, 256>>>(ei);

    k_prep<<<(KP * D1 + HHID + 255) / 256, 256>>>(W1);
    dim3 gw(D1 / 32, HHID / 32);
    k_prepW2<<<gw, 256>>>(W2);

    dim3 g1((NN + 127) / 128, D1 / 128);
    k_gemm1<<<g1, 256>>>(x);
    k_att1<<<NN, 128>>>(att_s1, att_d1);
    k_edge1<<<(EE + 255) / 256, 256>>>(ei);
    k_agg1<<<NN, 128>>>(b1);

    dim3 g2((NN + MM_BM - 1) / MM_BM, HHID / MM_BN);
    k_gemm2<<<g2, 256>>>(0);
    k_att2<<<(NN + 3) / 4, 128>>>(att_s2, att_d2);
    k_edge2<<<(EE + 255) / 256, 256>>>(ei);
    k_agg2<<<NN, 64>>>(b2);

    k_final<<<1, 128>>>(Wv1, bv1, Wv2, bv2, out);
}

// round 14
// speedup vs baseline: 2.1543x; 2.1543x over previous
#include <cuda_runtime.h>
#include <cuda_fp16.h>
#include <math.h>
#include <stdint.h>

#define NN 10000
#define EE 160000
#define FIN 70
#define KP 80            // FIN padded to multiple of 16
#define HHID 256
#define D1 1024          // HEADS*HID

typedef unsigned long long u64;

__device__ __forceinline__ uint32_t smem_u32(const void* p) {
    uint32_t a;
    asm("{ .reg .u64 t; cvta.to.shared.u64 t, %1; cvt.u32.u64 %0, t; }" : "=r"(a) : "l"(p));
    return a;
}
__device__ __forceinline__ float4 h4_to_f4(u64 v) {
    __half2 lo = reinterpret_cast<__half2*>(&v)[0];
    __half2 hi = reinterpret_cast<__half2*>(&v)[1];
    float2 a = __half22float2(lo), b = __half22float2(hi);
    return make_float4(a.x, a.y, b.x, b.y);
}

// ---------------- device scratch (no allocations allowed) ----------------
__device__ __align__(16) __half g_h1h[NN * D1];   // layer-1 linear out (fp16)
__device__ __align__(16) __half g_x1h[NN * D1];   // relu(agg1+b1) fp16 (GEMM2 A)
__device__ __align__(16) __half g_w1h[D1 * KP];   // W1^T fp16 [n][k], k padded to 80
__device__ __align__(16) __half g_w2h[HHID * D1]; // W2^T fp16 [n][k]
__device__ __align__(16) float g_as1[NN * 4];
__device__ __align__(16) float g_ad1[NN * 4];
__device__ __align__(16) float g_h2[NN * HHID];   // layer-2 linear out (fp32)
__device__ float g_as2[NN];
__device__ float g_ad2[NN];
__device__ __align__(16) float g_ex1s[EE * 4];    // exp(leaky) per edge, DST-SORTED
__device__ float g_ex2s[EE];
__device__ __align__(16) float g_exself1[NN * 4];
__device__ __align__(16) float g_den1[NN * 4];
__device__ float g_exself2[NN];
__device__ float g_den2[NN];
__device__ float g_pooled[HHID];
__device__ int   g_deg[NN];
__device__ int   g_offs[NN + 1];
__device__ int   g_cursor[NN];
__device__ int   g_srcs[EE];
__device__ int   g_pos[EE];      // original edge -> sorted slot

// ---------------- small utils ----------------
__global__ void k_zero() {
    int i = blockIdx.x * blockDim.x + threadIdx.x;
    if (i < NN)  g_deg[i] = 0;
    if (i < HHID) g_pooled[i] = 0.f;
}

__global__ void k_hist(const int* __restrict__ ei) {
    int i = blockIdx.x * blockDim.x + threadIdx.x;
    if (i < EE) atomicAdd(&g_deg[ei[EE + i]], 1);
}

__global__ void k_scan() {
    __shared__ int sbuf[1024];
    int t = threadIdx.x;
    int base = t * 10;
    int loc[10];
    int sum = 0;
#pragma unroll
    for (int q = 0; q < 10; q++) {
        int idx = base + q;
        int v = (idx < NN) ? g_deg[idx] : 0;
        loc[q] = sum; sum += v;
    }
    sbuf[t] = sum;
    __syncthreads();
    for (int off = 1; off < 1024; off <<= 1) {
        int tmp = (t >= off) ? sbuf[t - off] : 0;
        __syncthreads();
        sbuf[t] += tmp;
        __syncthreads();
    }
    int excl = sbuf[t] - sum;
#pragma unroll
    for (int q = 0; q < 10; q++) {
        int idx = base + q;
        if (idx < NN) { int o = excl + loc[q]; g_offs[idx] = o; g_cursor[idx] = o; }
    }
    if (t == 1023) g_offs[NN] = sbuf[1023];
}

__global__ void k_scatter(const int* __restrict__ ei) {
    int i = blockIdx.x * blockDim.x + threadIdx.x;
    if (i < EE) {
        int dnode = ei[EE + i];
        int pos = atomicAdd(&g_cursor[dnode], 1);
        g_srcs[pos] = ei[i];
        g_pos[i] = pos;
    }
}

// ---------------- W1 [70,1024] fp32 -> g_w1h [1024][80] fp16 ------------
__global__ void k_prepW1(const float* __restrict__ W1) {
    int id = blockIdx.x * blockDim.x + threadIdx.x;  // k-major over [KP][D1]
    if (id >= KP * D1) return;
    int k = id >> 10, n = id & 1023;
    float v = (k < FIN) ? W1[k * D1 + n] : 0.f;
    g_w1h[(size_t)n * KP + k] = __float2half(v);
}

// ---------------- W2 [1024,256] fp32 -> g_w2h [256][1024] fp16 ----------
__global__ void k_prepW2(const float* __restrict__ W2) {
    __shared__ float t[32][33];
    int k0 = blockIdx.x * 32, n0 = blockIdx.y * 32;
    int tx = threadIdx.x & 31, ty = threadIdx.x >> 5;   // 256 threads
#pragma unroll
    for (int i = 0; i < 4; i++)
        t[ty + 8 * i][tx] = W2[(k0 + ty + 8 * i) * HHID + n0 + tx];
    __syncthreads();
#pragma unroll
    for (int i = 0; i < 4; i++)
        g_w2h[(size_t)(n0 + ty + 8 * i) * D1 + k0 + tx] = __float2half(t[tx][ty + 8 * i]);
}

// ---------------- GEMM1 via HMMA: x[N,70] @ W1 -> g_h1h (fp16) ----------
#define G1_LDS 88
__global__ void __launch_bounds__(256) k_gemm1(const float* __restrict__ x) {
    __shared__ __align__(16) __half As[128][G1_LDS];
    __shared__ __align__(16) __half Bs[128][G1_LDS];
    int tid = threadIdx.x, lane = tid & 31, w = tid >> 5;
    int wm = w >> 2, wn = w & 3;
    int row0 = blockIdx.x * 128;
    int col0 = blockIdx.y * 128;

    for (int idx = tid; idx < 128 * KP; idx += 256) {
        int r = idx / KP, c = idx - r * KP;
        float v = 0.f;
        if (c < FIN && row0 + r < NN) v = x[(size_t)(row0 + r) * FIN + c];
        As[r][c] = __float2half(v);
    }
    for (int idx = tid; idx < 128 * 10; idx += 256) {
        int r = idx / 10, q = idx - r * 10;
        *reinterpret_cast<uint4*>(&Bs[r][q * 8]) =
            *reinterpret_cast<const uint4*>(&g_w1h[(size_t)(col0 + r) * KP + q * 8]);
    }
    __syncthreads();

    float acc[4][4][4];
#pragma unroll
    for (int i = 0; i < 4; i++)
#pragma unroll
        for (int j = 0; j < 4; j++)
#pragma unroll
            for (int q = 0; q < 4; q++) acc[i][j][q] = 0.f;

#pragma unroll
    for (int kh = 0; kh < 5; kh++) {
        uint32_t af[4][4], bf[4][2];
#pragma unroll
        for (int mt = 0; mt < 4; mt++) {
            int r = wm * 64 + mt * 16 + (lane & 15);
            int c = kh * 16 + (lane >> 4) * 8;
            uint32_t a = smem_u32(&As[r][c]);
            asm volatile("ldmatrix.sync.aligned.m8n8.x4.shared.b16 {%0,%1,%2,%3}, [%4];"
                : "=r"(af[mt][0]), "=r"(af[mt][1]), "=r"(af[mt][2]), "=r"(af[mt][3]) : "r"(a));
        }
#pragma unroll
        for (int nt = 0; nt < 4; nt++) {
            int r = wn * 32 + nt * 8 + (lane & 7);
            int c = kh * 16 + ((lane >> 3) & 1) * 8;
            uint32_t a = smem_u32(&Bs[r][c]);
            asm volatile("ldmatrix.sync.aligned.m8n8.x2.shared.b16 {%0,%1}, [%2];"
                : "=r"(bf[nt][0]), "=r"(bf[nt][1]) : "r"(a));
        }
#pragma unroll
        for (int mt = 0; mt < 4; mt++)
#pragma unroll
            for (int nt = 0; nt < 4; nt++)
                asm volatile(
                    "mma.sync.aligned.m16n8k16.row.col.f32.f16.f16.f32 "
                    "{%0,%1,%2,%3},{%4,%5,%6,%7},{%8,%9},{%0,%1,%2,%3};"
                    : "+f"(acc[mt][nt][0]), "+f"(acc[mt][nt][1]),
                      "+f"(acc[mt][nt][2]), "+f"(acc[mt][nt][3])
                    : "r"(af[mt][0]), "r"(af[mt][1]), "r"(af[mt][2]), "r"(af[mt][3]),
                      "r"(bf[nt][0]), "r"(bf[nt][1]));
    }

#pragma unroll
    for (int mt = 0; mt < 4; mt++) {
        int rr = row0 + wm * 64 + mt * 16 + (lane >> 2);
#pragma unroll
        for (int nt = 0; nt < 4; nt++) {
            int cc = col0 + wn * 32 + nt * 8 + 2 * (lane & 3);
            if (rr < NN)
                *reinterpret_cast<__half2*>(&g_h1h[(size_t)rr * D1 + cc]) =
                    __floats2half2_rn(acc[mt][nt][0], acc[mt][nt][1]);
            if (rr + 8 < NN)
                *reinterpret_cast<__half2*>(&g_h1h[(size_t)(rr + 8) * D1 + cc]) =
                    __floats2half2_rn(acc[mt][nt][2], acc[mt][nt][3]);
        }
    }
}

// ---------------- attention logits layer 1 + self-loop ex + den init ---
__global__ void k_att1(const float* __restrict__ as, const float* __restrict__ adv) {
    int wid = threadIdx.x >> 5, lane = threadIdx.x & 31;
    int d = blockIdx.x;
    const u64* hb = reinterpret_cast<const u64*>(g_h1h + (size_t)d * D1 + wid * 256);
    const float4* as4 = reinterpret_cast<const float4*>(as  + wid * 256);
    const float4* ad4 = reinterpret_cast<const float4*>(adv + wid * 256);
    float ps = 0.f, pd = 0.f;
#pragma unroll
    for (int t = 0; t < 2; t++) {
        int p = lane + 32 * t;
        float4 f = h4_to_f4(hb[p]);
        float4 a = as4[p], b = ad4[p];
        ps += f.x * a.x + f.y * a.y + f.z * a.z + f.w * a.w;
        pd += f.x * b.x + f.y * b.y + f.z * b.z + f.w * b.w;
    }
#pragma unroll
    for (int o = 16; o; o >>= 1) {
        ps += __shfl_xor_sync(0xffffffffu, ps, o);
        pd += __shfl_xor_sync(0xffffffffu, pd, o);
    }
    if (lane == 0) {
        g_as1[d * 4 + wid] = ps; g_ad1[d * 4 + wid] = pd;
        float e = ps + pd;
        e = e > 0.f ? e : 0.2f * e;
        float ex = expf(e);
        g_exself1[d * 4 + wid] = ex;
        g_den1[d * 4 + wid] = ex;
    }
}

// ---------------- edge kernel layer 1: ex (sorted) + denom atomics -----
__global__ void k_edge1(const int* __restrict__ ei) {
    int i = blockIdx.x * blockDim.x + threadIdx.x;
    if (i >= EE) return;
    int s = ei[i], d = ei[EE + i];
    float4 a = *reinterpret_cast<const float4*>(&g_as1[s * 4]);
    float4 b = *reinterpret_cast<const float4*>(&g_ad1[d * 4]);
    float e0 = a.x + b.x; e0 = e0 > 0.f ? e0 : 0.2f * e0; e0 = expf(e0);
    float e1 = a.y + b.y; e1 = e1 > 0.f ? e1 : 0.2f * e1; e1 = expf(e1);
    float e2 = a.z + b.z; e2 = e2 > 0.f ? e2 : 0.2f * e2; e2 = expf(e2);
    float e3 = a.w + b.w; e3 = e3 > 0.f ? e3 : 0.2f * e3; e3 = expf(e3);
    int pos = g_pos[i];
    *reinterpret_cast<float4*>(&g_ex1s[(size_t)pos * 4]) = make_float4(e0, e1, e2, e3);
    atomicAdd(&g_den1[d * 4 + 0], e0);
    atomicAdd(&g_den1[d * 4 + 1], e1);
    atomicAdd(&g_den1[d * 4 + 2], e2);
    atomicAdd(&g_den1[d * 4 + 3], e3);
}

// ---------------- layer-1 aggregation: single pass, vectorized ---------
// thread t handles channels [4t, 4t+4) -> one head per thread (h = t>>6)
__global__ void k_agg1(const float* __restrict__ b1) {
    int d = blockIdx.x, t = threadIdx.x;
    int beg = g_offs[d], cnt = g_offs[d + 1] - beg;
    int h = t >> 6;
    const u64* hb = reinterpret_cast<const u64*>(g_h1h);

    // self-loop term
    float ex = g_exself1[d * 4 + h];
    float4 f = h4_to_f4(hb[(size_t)d * 256 + t]);
    float ax = ex * f.x, ay = ex * f.y, az = ex * f.z, aw = ex * f.w;

#pragma unroll 4
    for (int i = 0; i < cnt; i++) {
        int s = g_srcs[beg + i];
        float e = g_ex1s[(size_t)(beg + i) * 4 + h];
        float4 g = h4_to_f4(hb[(size_t)s * 256 + t]);
        ax += e * g.x; ay += e * g.y; az += e * g.z; aw += e * g.w;
    }

    float inv = 1.f / (g_den1[d * 4 + h] + 1e-16f);
    float4 bb = *reinterpret_cast<const float4*>(&b1[4 * t]);
    __half2 lo = __floats2half2_rn(fmaxf(ax * inv + bb.x, 0.f),
                                   fmaxf(ay * inv + bb.y, 0.f));
    __half2 hi = __floats2half2_rn(fmaxf(az * inv + bb.z, 0.f),
                                   fmaxf(aw * inv + bb.w, 0.f));
    u64 outv;
    reinterpret_cast<__half2*>(&outv)[0] = lo;
    reinterpret_cast<__half2*>(&outv)[1] = hi;
    *reinterpret_cast<u64*>(&g_x1h[(size_t)d * D1 + 4 * t]) = outv;
}

// ---------------- GEMM2 via mma.sync (HMMA fp16) ------------------------
#define MM_BM 128
#define MM_BN 128
#define MM_BK 32
#define MM_LDS 40      // row stride in halves (32 + 8 pad)
__global__ void __launch_bounds__(256) k_gemm2(int dummy) {
    __shared__ __align__(16) __half As[MM_BM][MM_LDS];
    __shared__ __align__(16) __half Bs[MM_BN][MM_LDS];
    int tid = threadIdx.x, lane = tid & 31, w = tid >> 5;
    int wm = w >> 2, wn = w & 3;
    int row0 = blockIdx.x * MM_BM;
    int col0 = blockIdx.y * MM_BN;

    float acc[4][4][4];
#pragma unroll
    for (int i = 0; i < 4; i++)
#pragma unroll
        for (int j = 0; j < 4; j++)
#pragma unroll
            for (int q = 0; q < 4; q++) acc[i][j][q] = 0.f;

    int rA0 = (tid + 0)   >> 2, qA0 = (tid + 0)   & 3;
    int rA1 = (tid + 256) >> 2, qA1 = (tid + 256) & 3;

    uint4 pa0, pa1, pb0, pb1;
    {
        pa0 = make_uint4(0, 0, 0, 0); pa1 = make_uint4(0, 0, 0, 0);
        if (row0 + rA0 < NN)
            pa0 = *reinterpret_cast<const uint4*>(&g_x1h[(size_t)(row0 + rA0) * D1 + qA0 * 8]);
        if (row0 + rA1 < NN)
            pa1 = *reinterpret_cast<const uint4*>(&g_x1h[(size_t)(row0 + rA1) * D1 + qA1 * 8]);
        pb0 = *reinterpret_cast<const uint4*>(&g_w2h[(size_t)(col0 + rA0) * D1 + qA0 * 8]);
        pb1 = *reinterpret_cast<const uint4*>(&g_w2h[(size_t)(col0 + rA1) * D1 + qA1 * 8]);
    }

    for (int kc = 0; kc < D1; kc += MM_BK) {
        *reinterpret_cast<uint4*>(&As[rA0][qA0 * 8]) = pa0;
        *reinterpret_cast<uint4*>(&As[rA1][qA1 * 8]) = pa1;
        *reinterpret_cast<uint4*>(&Bs[rA0][qA0 * 8]) = pb0;
        *reinterpret_cast<uint4*>(&Bs[rA1][qA1 * 8]) = pb1;
        __syncthreads();

        if (kc + MM_BK < D1) {
            int kn = kc + MM_BK;
            pa0 = make_uint4(0, 0, 0, 0); pa1 = make_uint4(0, 0, 0, 0);
            if (row0 + rA0 < NN)
                pa0 = *reinterpret_cast<const uint4*>(&g_x1h[(size_t)(row0 + rA0) * D1 + kn + qA0 * 8]);
            if (row0 + rA1 < NN)
                pa1 = *reinterpret_cast<const uint4*>(&g_x1h[(size_t)(row0 + rA1) * D1 + kn + qA1 * 8]);
            pb0 = *reinterpret_cast<const uint4*>(&g_w2h[(size_t)(col0 + rA0) * D1 + kn + qA0 * 8]);
            pb1 = *reinterpret_cast<const uint4*>(&g_w2h[(size_t)(col0 + rA1) * D1 + kn + qA1 * 8]);
        }

#pragma unroll
        for (int kh = 0; kh < 2; kh++) {
            uint32_t af[4][4], bf[4][2];
#pragma unroll
            for (int mt = 0; mt < 4; mt++) {
                int r = wm * 64 + mt * 16 + (lane & 15);
                int c = kh * 16 + (lane >> 4) * 8;
                uint32_t a = smem_u32(&As[r][c]);
                asm volatile("ldmatrix.sync.aligned.m8n8.x4.shared.b16 {%0,%1,%2,%3}, [%4];"
                    : "=r"(af[mt][0]), "=r"(af[mt][1]), "=r"(af[mt][2]), "=r"(af[mt][3]) : "r"(a));
            }
#pragma unroll
            for (int nt = 0; nt < 4; nt++) {
                int r = wn * 32 + nt * 8 + (lane & 7);
                int c = kh * 16 + ((lane >> 3) & 1) * 8;
                uint32_t a = smem_u32(&Bs[r][c]);
                asm volatile("ldmatrix.sync.aligned.m8n8.x2.shared.b16 {%0,%1}, [%2];"
                    : "=r"(bf[nt][0]), "=r"(bf[nt][1]) : "r"(a));
            }
#pragma unroll
            for (int mt = 0; mt < 4; mt++)
#pragma unroll
                for (int nt = 0; nt < 4; nt++)
                    asm volatile(
                        "mma.sync.aligned.m16n8k16.row.col.f32.f16.f16.f32 "
                        "{%0,%1,%2,%3},{%4,%5,%6,%7},{%8,%9},{%0,%1,%2,%3};"
                        : "+f"(acc[mt][nt][0]), "+f"(acc[mt][nt][1]),
                          "+f"(acc[mt][nt][2]), "+f"(acc[mt][nt][3])
                        : "r"(af[mt][0]), "r"(af[mt][1]), "r"(af[mt][2]), "r"(af[mt][3]),
                          "r"(bf[nt][0]), "r"(bf[nt][1]));
        }
        __syncthreads();
    }

#pragma unroll
    for (int mt = 0; mt < 4; mt++) {
        int rr = row0 + wm * 64 + mt * 16 + (lane >> 2);
#pragma unroll
        for (int nt = 0; nt < 4; nt++) {
            int cc = col0 + wn * 32 + nt * 8 + 2 * (lane & 3);
            if (rr < NN)
                *reinterpret_cast<float2*>(&g_h2[(size_t)rr * HHID + cc]) =
                    make_float2(acc[mt][nt][0], acc[mt][nt][1]);
            if (rr + 8 < NN)
                *reinterpret_cast<float2*>(&g_h2[(size_t)(rr + 8) * HHID + cc]) =
                    make_float2(acc[mt][nt][2], acc[mt][nt][3]);
        }
    }
}

// ---------------- attention logits layer 2 + self ex + den init --------
__global__ void k_att2(const float* __restrict__ as, const float* __restrict__ adv) {
    int wid = threadIdx.x >> 5, lane = threadIdx.x & 31;
    int d = blockIdx.x * 4 + wid;
    if (d >= NN) return;
    const float4* h4  = reinterpret_cast<const float4*>(g_h2 + (size_t)d * HHID);
    const float4* as4 = reinterpret_cast<const float4*>(as);
    const float4* ad4 = reinterpret_cast<const float4*>(adv);
    float ps = 0.f, pd = 0.f;
#pragma unroll
    for (int t = 0; t < 2; t++) {
        int p = lane + 32 * t;
        float4 f = h4[p];
        float4 a = as4[p], b = ad4[p];
        ps += f.x * a.x + f.y * a.y + f.z * a.z + f.w * a.w;
        pd += f.x * b.x + f.y * b.y + f.z * b.z + f.w * b.w;
    }
#pragma unroll
    for (int o = 16; o; o >>= 1) {
        ps += __shfl_xor_sync(0xffffffffu, ps, o);
        pd += __shfl_xor_sync(0xffffffffu, pd, o);
    }
    if (lane == 0) {
        g_as2[d] = ps; g_ad2[d] = pd;
        float e = ps + pd;
        e = e > 0.f ? e : 0.2f * e;
        float ex = expf(e);
        g_exself2[d] = ex;
        g_den2[d] = ex;
    }
}

// ---------------- edge kernel layer 2 ----------------------------------
__global__ void k_edge2(const int* __restrict__ ei) {
    int i = blockIdx.x * blockDim.x + threadIdx.x;
    if (i >= EE) return;
    int s = ei[i], d = ei[EE + i];
    float e = g_as2[s] + g_ad2[d];
    e = e > 0.f ? e : 0.2f * e;
    float ex = expf(e);
    g_ex2s[g_pos[i]] = ex;
    atomicAdd(&g_den2[d], ex);
}

// ---------------- layer-2 aggregation + ReLU + mean pool ---------------
__global__ void k_agg2(const float* __restrict__ b2) {
    int d = blockIdx.x, tid = threadIdx.x;
    int beg = g_offs[d], cnt = g_offs[d + 1] - beg;
    float acc = g_exself2[d] * g_h2[(size_t)d * HHID + tid];
#pragma unroll 4
    for (int i = 0; i < cnt; i++) {
        int s = g_srcs[beg + i];
        acc += g_ex2s[beg + i] * g_h2[(size_t)s * HHID + tid];
    }
    float inv = 1.f / (g_den2[d] + 1e-16f);
    float v = acc * inv + b2[tid];
    v = v > 0.f ? v : 0.f;
    atomicAdd(&g_pooled[tid], v * (1.0f / NN));
}

// ---------------- final MLP ----------------
__global__ void k_final(const float* __restrict__ Wv1, const float* __restrict__ bv1,
                        const float* __restrict__ Wv2, const float* __restrict__ bv2,
                        float* __restrict__ out) {
    __shared__ float sp[HHID];
    __shared__ float wred[4];
    int t = threadIdx.x;   // 128 threads
    for (int c = t; c < HHID; c += 128) sp[c] = g_pooled[c];
    __syncthreads();
    float a = 0.f;
    for (int k = 0; k < HHID; k++) a += sp[k] * Wv1[k * 128 + t];
    a += bv1[t];
    float g = a * normcdff(a);
    float v = g * Wv2[t];
    int lane = t & 31, wid = t >> 5;
#pragma unroll
    for (int o = 16; o; o >>= 1) v += __shfl_xor_sync(0xffffffffu, v, o);
    if (lane == 0) wred[wid] = v;
    __syncthreads();
    if (t == 0) out[0] = wred[0] + wred[1] + wred[2] + wred[3] + bv2[0];
}

// ---------------- launch ----------------
extern "C" void kernel_launch(void* const* d_in, const int* in_sizes, int n_in,
                              void* d_out, int out_size) {
    const float* x       = (const float*)d_in[0];
    const int*   ei      = (const int*)  d_in[1];
    // d_in[2] edge_attr unused (GATConv built without edge_dim)
    const float* W1      = (const float*)d_in[3];
    const float* att_s1  = (const float*)d_in[4];
    const float* att_d1  = (const float*)d_in[5];
    const float* b1      = (const float*)d_in[6];
    const float* W2      = (const float*)d_in[7];
    const float* att_s2  = (const float*)d_in[8];
    const float* att_d2  = (const float*)d_in[9];
    const float* b2      = (const float*)d_in[10];
    const float* Wv1     = (const float*)d_in[11];
    const float* bv1     = (const float*)d_in[12];
    const float* Wv2     = (const float*)d_in[13];
    const float* bv2     = (const float*)d_in[14];
    float* out = (float*)d_out;

    k_zero<<<(NN + 255) / 256, 256>>>();
    k_hist<<<(EE + 255) / 256, 256>>>(ei);
    k_scan<<<1, 1024>>>();
    k_scatter<<<(EE + 255) / 256, 256>>>(ei);

    k_prepW1<<<(KP * D1 + 255) / 256, 256>>>(W1);
    dim3 gw(D1 / 32, HHID / 32);
    k_prepW2<<<gw, 256>>>(W2);

    dim3 g1((NN + 127) / 128, D1 / 128);
    k_gemm1<<<g1, 256>>>(x);
    k_att1<<<NN, 128>>>(att_s1, att_d1);
    k_edge1<<<(EE + 255) / 256, 256>>>(ei);
    k_agg1<<<NN, 256>>>(b1);

    dim3 g2((NN + MM_BM - 1) / MM_BM, HHID / MM_BN);
    k_gemm2<<<g2, 256>>>(0);
    k_att2<<<(NN + 3) / 4, 128>>>(att_s2, att_d2);
    k_edge2<<<(EE + 255) / 256, 256>>>(ei);
    k_agg2<<<NN, 256>>>(b2);

    k_final<<<1, 128>>>(Wv1, bv1, Wv2, bv2, out);
}